// round 2
// baseline (speedup 1.0000x reference)
#include <cuda_runtime.h>

#define NNODES 100000
#define NEDGES 1250000
#define DFEAT  64

// Persistent scratch: aggregated neighbor sums [NNODES, 64] (25.6 MB)
__device__ float g_aggr[NNODES * DFEAT];
__device__ int g_is64;

// ---------------------------------------------------------------------------
// Detect whether edge_index is int64 or int32 (JAX x64-disabled silently gives
// int32). Indices are in [0, 100000) < 2^17, so for int64 layout every hi-word
// is zero. Probability of a false positive with real int32 data: ~(1e-5)^64.
// ---------------------------------------------------------------------------
__global__ void detect_kernel(const int* __restrict__ ei) {
    if (threadIdx.x == 0) {
        int ok = 1;
        #pragma unroll 1
        for (int i = 0; i < 64; i++)
            if (ei[2 * i + 1] != 0) ok = 0;
        g_is64 = ok;
    }
}

// ---------------------------------------------------------------------------
// Zero the aggregation scratch. 6.4M floats = 1.6M float4; exact grid.
// ---------------------------------------------------------------------------
__global__ void zero_kernel() {
    unsigned i = blockIdx.x * blockDim.x + threadIdx.x;
    reinterpret_cast<float4*>(g_aggr)[i] = make_float4(0.f, 0.f, 0.f, 0.f);
}

// ---------------------------------------------------------------------------
// Scatter-add: 16 threads per edge, each thread moves one float4 (16B) of the
// 256B feature row via LDG.128 + RED.128 (red.global.add.v4.f32, sm_90+).
// x (25.6MB) and g_aggr (25.6MB) both fit in the 126MB L2.
// ---------------------------------------------------------------------------
__global__ void scatter_kernel(const float4* __restrict__ x4,
                               const void* __restrict__ ei) {
    unsigned tid = blockIdx.x * blockDim.x + threadIdx.x;
    unsigned e = tid >> 4;
    unsigned c = tid & 15;

    long long src, dst;
    if (g_is64) {
        const long long* p = (const long long*)ei;
        src = p[e];
        dst = p[NEDGES + e];
    } else {
        const int* p = (const int*)ei;
        src = p[e];
        dst = p[NEDGES + e];
    }

    float4 v = x4[(size_t)src * 16 + c];
    float* q = g_aggr + (size_t)dst * 64 + (size_t)c * 4;
    asm volatile("red.global.add.v4.f32 [%0], {%1, %2, %3, %4};"
                 :: "l"(q), "f"(v.x), "f"(v.y), "f"(v.z), "f"(v.w)
                 : "memory");
}

// ---------------------------------------------------------------------------
// Fused epilogue: out = tanh(aggr @ W_l + b_l + x @ W_r)
// Block = 128 threads handles 64 nodes x 64 outputs.
// Thread (t): outputs [ (t&15)*4 .. +3 ], nodes [ (t>>4)*8 .. +7 ]
//   -> 8x4 fp32 accumulators, 64 FFMA + ~18 LDS per k-iteration.
// Smem: W_l (16KB) + W_r (16KB) + bias + x tile + aggr tile (65-float pitch,
// conflict-free scalar reads). Total ~66.3KB dynamic smem.
// ---------------------------------------------------------------------------
#define TNODES 64
#define GT     128

__global__ __launch_bounds__(GT) void fused_gemm_kernel(
    const float* __restrict__ x,
    const float* __restrict__ Wl,
    const float* __restrict__ bl,
    const float* __restrict__ Wr,
    float* __restrict__ out) {
    extern __shared__ float sm[];
    float* sWl = sm;                 // 4096
    float* sWr = sWl + 4096;         // 4096
    float* sb  = sWr + 4096;         // 64
    float* xs  = sb + 64;            // 64*65
    float* as_ = xs + 64 * 65;       // 64*65

    const int t = threadIdx.x;
    const int node0 = blockIdx.x * TNODES;

    // Stage W matrices (1024 float4 each; 8 per thread)
    const float4* Wl4 = (const float4*)Wl;
    const float4* Wr4 = (const float4*)Wr;
    #pragma unroll
    for (int i = 0; i < 8; i++) {
        ((float4*)sWl)[t + i * GT] = Wl4[t + i * GT];
        ((float4*)sWr)[t + i * GT] = Wr4[t + i * GT];
    }
    if (t < 64) sb[t] = bl[t];

    // Stage x / aggr tiles: 64 nodes x 16 float4 = 1024 float4 each
    #pragma unroll
    for (int i = 0; i < 8; i++) {
        int idx = t + i * GT;
        int n = idx >> 4, c = idx & 15;
        int gnode = node0 + n;
        float4 xv = make_float4(0.f, 0.f, 0.f, 0.f);
        float4 av = make_float4(0.f, 0.f, 0.f, 0.f);
        if (gnode < NNODES) {
            xv = ((const float4*)x)[(size_t)gnode * 16 + c];
            av = ((const float4*)g_aggr)[(size_t)gnode * 16 + c];
        }
        float* xr = &xs[n * 65 + c * 4];
        xr[0] = xv.x; xr[1] = xv.y; xr[2] = xv.z; xr[3] = xv.w;
        float* ar = &as_[n * 65 + c * 4];
        ar[0] = av.x; ar[1] = av.y; ar[2] = av.z; ar[3] = av.w;
    }
    __syncthreads();

    const int to = (t & 15) * 4;   // output column base
    const int tn = (t >> 4) * 8;   // node base within tile

    float acc[8][4];
    #pragma unroll
    for (int j = 0; j < 8; j++) {
        acc[j][0] = sb[to + 0];
        acc[j][1] = sb[to + 1];
        acc[j][2] = sb[to + 2];
        acc[j][3] = sb[to + 3];
    }

    #pragma unroll 4
    for (int k = 0; k < 64; k++) {
        float4 wl = *(const float4*)&sWl[k * 64 + to];
        float4 wr = *(const float4*)&sWr[k * 64 + to];
        #pragma unroll
        for (int j = 0; j < 8; j++) {
            float a = as_[(tn + j) * 65 + k];
            float b = xs[(tn + j) * 65 + k];
            acc[j][0] = fmaf(a, wl.x, acc[j][0]);
            acc[j][1] = fmaf(a, wl.y, acc[j][1]);
            acc[j][2] = fmaf(a, wl.z, acc[j][2]);
            acc[j][3] = fmaf(a, wl.w, acc[j][3]);
            acc[j][0] = fmaf(b, wr.x, acc[j][0]);
            acc[j][1] = fmaf(b, wr.y, acc[j][1]);
            acc[j][2] = fmaf(b, wr.z, acc[j][2]);
            acc[j][3] = fmaf(b, wr.w, acc[j][3]);
        }
    }

    #pragma unroll
    for (int j = 0; j < 8; j++) {
        int gnode = node0 + tn + j;
        if (gnode < NNODES) {
            float4 r;
            r.x = tanhf(acc[j][0]);
            r.y = tanhf(acc[j][1]);
            r.z = tanhf(acc[j][2]);
            r.w = tanhf(acc[j][3]);
            ((float4*)out)[(size_t)gnode * 16 + (to >> 2)] = r;
        }
    }
}

// ---------------------------------------------------------------------------
extern "C" void kernel_launch(void* const* d_in, const int* in_sizes, int n_in,
                              void* d_out, int out_size) {
    const float* x  = (const float*)d_in[0];
    const void*  ei = d_in[1];                 // int64 or int32, detected
    const float* Wl = (const float*)d_in[2];
    const float* bl = (const float*)d_in[3];
    const float* Wr = (const float*)d_in[4];
    float* out = (float*)d_out;

    static const int kSmem = (4096 + 4096 + 64 + 2 * 64 * 65) * 4;
    cudaFuncSetAttribute(fused_gemm_kernel,
                         cudaFuncAttributeMaxDynamicSharedMemorySize, kSmem);

    detect_kernel<<<1, 32>>>((const int*)ei);

    // 6.4M floats -> 1.6M float4; 1600000 / 256 = 6250 exact
    zero_kernel<<<6250, 256>>>();

    // 1.25M edges * 16 threads = 20M; 20000000 / 256 = 78125 exact
    scatter_kernel<<<78125, 256>>>((const float4*)x, ei);

    // (100000 + 63) / 64 = 1563 blocks
    fused_gemm_kernel<<<1563, GT, kSmem>>>(x, Wl, bl, Wr, out);
}

// round 7
// speedup vs baseline: 1.0158x; 1.0158x over previous
#include <cuda_runtime.h>
#include <cuda_fp16.h>

#define NN 100000
#define NE 1250000

// ---------------- persistent scratch (no runtime alloc allowed) -------------
__device__ float  g_aggr[NN * 64];        // 25.6 MB
__device__ __half g_xh[NN * 64];          // 12.8 MB fp16 copy of x
__device__ int    g_cnt[NN];
__device__ int    g_excl[NN];             // exclusive-within-block scan
__device__ int    g_bsum[128];
__device__ int    g_bofs[128];
__device__ int    g_off[NN + 1];
__device__ int    g_cur[NN];
__device__ int    g_csr[NE];
__device__ int    g_is64;

// ---------------------------------------------------------------------------
// int64 vs int32 edge_index detection (indices < 2^17 => hi-words all zero)
// ---------------------------------------------------------------------------
__global__ void detect_kernel(const int* __restrict__ ei) {
    if (threadIdx.x == 0) {
        int ok = 1;
        #pragma unroll 1
        for (int i = 0; i < 64; i++)
            if (ei[2 * i + 1] != 0) ok = 0;
        g_is64 = ok;
    }
}

__global__ void zero_cnt_kernel() {
    int i = blockIdx.x * blockDim.x + threadIdx.x;
    if (i < NN) g_cnt[i] = 0;
}

// fp32 -> fp16 copy of x (one float4 = 4 floats per thread, exact grid)
__global__ void convert_kernel(const float4* __restrict__ x4) {
    int i = blockIdx.x * blockDim.x + threadIdx.x;   // 0 .. 1.6M-1
    float4 f = x4[i];
    __half2* o = (__half2*)g_xh;
    o[i * 2 + 0] = __float22half2_rn(make_float2(f.x, f.y));
    o[i * 2 + 1] = __float22half2_rn(make_float2(f.z, f.w));
}

// ---------------------------------------------------------------------------
// CSR build: histogram -> 2-level block scan -> fill
// ---------------------------------------------------------------------------
__global__ void hist_kernel(const void* __restrict__ ei) {
    int e = blockIdx.x * blockDim.x + threadIdx.x;
    if (e >= NE) return;
    int d;
    if (g_is64) d = (int)((const long long*)ei)[NE + e];
    else        d = ((const int*)ei)[NE + e];
    atomicAdd(&g_cnt[d], 1);
}

__global__ __launch_bounds__(1024) void scan1_kernel() {
    __shared__ int s[1024];
    int t = threadIdx.x, b = blockIdx.x;
    int i = b * 1024 + t;
    int v = (i < NN) ? g_cnt[i] : 0;
    s[t] = v;
    __syncthreads();
    #pragma unroll
    for (int o = 1; o < 1024; o <<= 1) {
        int x = (t >= o) ? s[t - o] : 0;
        __syncthreads();
        s[t] += x;
        __syncthreads();
    }
    if (i < NN) g_excl[i] = s[t] - v;
    if (t == 1023) g_bsum[b] = s[1023];
}

__global__ void scan2_kernel(int nblk) {
    __shared__ int s[128];
    int t = threadIdx.x;
    int v = (t < nblk) ? g_bsum[t] : 0;
    s[t] = v;
    __syncthreads();
    #pragma unroll
    for (int o = 1; o < 128; o <<= 1) {
        int x = (t >= o) ? s[t - o] : 0;
        __syncthreads();
        s[t] += x;
        __syncthreads();
    }
    if (t < nblk) g_bofs[t] = s[t] - v;
    if (t == 0) g_off[NN] = NE;
}

__global__ __launch_bounds__(1024) void scan3_kernel() {
    int i = blockIdx.x * 1024 + threadIdx.x;
    if (i < NN) {
        int off = g_excl[i] + g_bofs[blockIdx.x];
        g_off[i] = off;
        g_cur[i] = off;
    }
}

__global__ void fill_kernel(const void* __restrict__ ei) {
    int e = blockIdx.x * blockDim.x + threadIdx.x;
    if (e >= NE) return;
    int s, d;
    if (g_is64) {
        const long long* p = (const long long*)ei;
        s = (int)p[e]; d = (int)p[NE + e];
    } else {
        const int* p = (const int*)ei;
        s = p[e]; d = p[NE + e];
    }
    int pos = atomicAdd(&g_cur[d], 1);
    g_csr[pos] = s;
}

// ---------------------------------------------------------------------------
// Aggregation: one warp per destination node. Lane owns one half2 column
// (64 halves per row = 32 half2). 2-edge unroll -> MLP 2 on the gather.
// Writes each aggr row exactly once (deg-0 rows get zeros; replaces zero+RED).
// ---------------------------------------------------------------------------
__global__ __launch_bounds__(256) void aggregate_kernel() {
    int d = blockIdx.x * 8 + (threadIdx.x >> 5);
    int lane = threadIdx.x & 31;
    const __half2* xh2 = (const __half2*)g_xh;
    int beg = g_off[d];
    int end = g_off[d + 1];
    float2 acc = make_float2(0.f, 0.f);
    int i = beg;
    for (; i + 1 < end; i += 2) {
        int s0 = g_csr[i];
        int s1 = g_csr[i + 1];
        __half2 h0 = xh2[(size_t)s0 * 32 + lane];
        __half2 h1 = xh2[(size_t)s1 * 32 + lane];
        float2 f0 = __half22float2(h0);
        float2 f1 = __half22float2(h1);
        acc.x += f0.x + f1.x;
        acc.y += f0.y + f1.y;
    }
    if (i < end) {
        int s0 = g_csr[i];
        float2 f0 = __half22float2(xh2[(size_t)s0 * 32 + lane]);
        acc.x += f0.x;
        acc.y += f0.y;
    }
    ((float2*)g_aggr)[(size_t)d * 32 + lane] = acc;
}

// ---------------------------------------------------------------------------
// Fused GEMM epilogue: out = tanh(aggr @ W_l + b_l + x @ W_r)
// 256 threads, 128-node tile, 2 CTAs/SM (102.4 KB smem each).
// Thread: outputs [(t&15)*4 .. +3], nodes { (t>>4) + 16*j, j=0..7 }.
// Interleaved node mapping => the two distinct LDS.128 addresses per warp
// differ by one pitch row (272B -> different bank quad) => conflict-free.
// Per 4-k chunk: 256 FFMA vs 24 LDS (91% FMA share).
// ---------------------------------------------------------------------------
#define GT 256
#define TN 128
#define PITCH 68   // floats; 272B rows, 16B-aligned

__global__ __launch_bounds__(GT, 2) void fused_gemm_kernel(
    const float* __restrict__ x,
    const float* __restrict__ Wl,
    const float* __restrict__ bl,
    const float* __restrict__ Wr,
    float* __restrict__ out) {
    extern __shared__ float sm[];
    float* sWl = sm;                        // 4096
    float* sWr = sWl + 4096;                // 4096
    float* sb  = sWr + 4096;                // 64
    float* xs  = sb + 64;                   // 128*68
    float* as_ = xs + TN * PITCH;           // 128*68

    const int t = threadIdx.x;
    const int node0 = blockIdx.x * TN;

    // Stage weights: 1024 float4 each, 4 per thread
    const float4* Wl4 = (const float4*)Wl;
    const float4* Wr4 = (const float4*)Wr;
    #pragma unroll
    for (int i = 0; i < 4; i++) {
        ((float4*)sWl)[t + i * GT] = Wl4[t + i * GT];
        ((float4*)sWr)[t + i * GT] = Wr4[t + i * GT];
    }
    if (t < 64) sb[t] = bl[t];

    // Stage x / aggr tiles: 128 rows x 16 float4 each = 2048 float4 per array
    #pragma unroll
    for (int i = 0; i < 8; i++) {
        int idx = t + i * GT;
        int n = idx >> 4, c = idx & 15;
        int gn = node0 + n;
        float4 xv = make_float4(0.f, 0.f, 0.f, 0.f);
        float4 av = make_float4(0.f, 0.f, 0.f, 0.f);
        if (gn < NN) {
            xv = ((const float4*)x)[(size_t)gn * 16 + c];
            av = ((const float4*)g_aggr)[(size_t)gn * 16 + c];
        }
        *(float4*)&xs[n * PITCH + c * 4] = xv;
        *(float4*)&as_[n * PITCH + c * 4] = av;
    }
    __syncthreads();

    const int to = (t & 15) * 4;   // output column base
    const int tg = (t >> 4);       // node offset within tile (0..15)

    float acc[8][4];
    #pragma unroll
    for (int j = 0; j < 8; j++) {
        acc[j][0] = sb[to + 0];
        acc[j][1] = sb[to + 1];
        acc[j][2] = sb[to + 2];
        acc[j][3] = sb[to + 3];
    }

    for (int k = 0; k < 64; k += 4) {
        float4 wl[4], wr[4];
        #pragma unroll
        for (int q = 0; q < 4; q++) {
            wl[q] = *(const float4*)&sWl[(k + q) * 64 + to];
            wr[q] = *(const float4*)&sWr[(k + q) * 64 + to];
        }
        #pragma unroll
        for (int j = 0; j < 8; j++) {
            int row = tg + j * 16;
            float4 a4 = *(const float4*)&as_[row * PITCH + k];
            float4 b4 = *(const float4*)&xs[row * PITCH + k];
            float av[4] = {a4.x, a4.y, a4.z, a4.w};
            float bv[4] = {b4.x, b4.y, b4.z, b4.w};
            #pragma unroll
            for (int q = 0; q < 4; q++) {
                acc[j][0] = fmaf(av[q], wl[q].x, acc[j][0]);
                acc[j][1] = fmaf(av[q], wl[q].y, acc[j][1]);
                acc[j][2] = fmaf(av[q], wl[q].z, acc[j][2]);
                acc[j][3] = fmaf(av[q], wl[q].w, acc[j][3]);
                acc[j][0] = fmaf(bv[q], wr[q].x, acc[j][0]);
                acc[j][1] = fmaf(bv[q], wr[q].y, acc[j][1]);
                acc[j][2] = fmaf(bv[q], wr[q].z, acc[j][2]);
                acc[j][3] = fmaf(bv[q], wr[q].w, acc[j][3]);
            }
        }
    }

    #pragma unroll
    for (int j = 0; j < 8; j++) {
        int gn = node0 + tg + j * 16;
        if (gn < NN) {
            float4 r;
            r.x = tanhf(acc[j][0]);
            r.y = tanhf(acc[j][1]);
            r.z = tanhf(acc[j][2]);
            r.w = tanhf(acc[j][3]);
            ((float4*)out)[(size_t)gn * 16 + (to >> 2)] = r;
        }
    }
}

// ---------------------------------------------------------------------------
extern "C" void kernel_launch(void* const* d_in, const int* in_sizes, int n_in,
                              void* d_out, int out_size) {
    const float* x  = (const float*)d_in[0];
    const void*  ei = d_in[1];
    const float* Wl = (const float*)d_in[2];
    const float* bl = (const float*)d_in[3];
    const float* Wr = (const float*)d_in[4];
    float* out = (float*)d_out;

    static const int kSmem = (4096 + 4096 + 64 + 2 * TN * PITCH) * 4;
    cudaFuncSetAttribute(fused_gemm_kernel,
                         cudaFuncAttributeMaxDynamicSharedMemorySize, kSmem);

    const int nScanBlk = (NN + 1023) / 1024;          // 98

    detect_kernel<<<1, 32>>>((const int*)ei);
    zero_cnt_kernel<<<(NN + 255) / 256, 256>>>();
    convert_kernel<<<6250, 256>>>((const float4*)x);  // 1.6M float4 exact
    hist_kernel<<<(NE + 255) / 256, 256>>>(ei);
    scan1_kernel<<<nScanBlk, 1024>>>();
    scan2_kernel<<<1, 128>>>(nScanBlk);
    scan3_kernel<<<nScanBlk, 1024>>>();
    fill_kernel<<<(NE + 255) / 256, 256>>>(ei);
    aggregate_kernel<<<NN / 8, 256>>>();              // 12500 blocks, warp/dst
    fused_gemm_kernel<<<(NN + TN - 1) / TN, GT, kSmem>>>(x, Wl, bl, Wr, out);
}